// round 4
// baseline (speedup 1.0000x reference)
#include <cuda_runtime.h>
#include <cuda_bf16.h>
#include <cstdint>

// ---------------------------------------------------------------------------
// SCCN forward: 4 ranks, C=128, L=2 layers, sigmoid update, softmax head.
//
// Per layer:
//   phase A: 10 dense GEMMs (x_r @ W) into g_y scratch
//   phase B: zero g_m accumulator
//   phase C: 10 COO SPMM scatter-adds (red.global.add.v4.f32) into g_m
//   phase D: sigmoid(g_m) -> g_x  (next layer's x)
// Head: softmax(x0 @ W_out + b_out) -> d_out
// ---------------------------------------------------------------------------

#define C128 128

static const int N0 = 40000, N1 = 120000, N2 = 80000, N3 = 20000;
static const int NTOT = 260000;                       // sum of N
static const int YROWS = 720000;                      // GEMM scratch rows

// x / m buffers: 260000 * 128 floats = 133.1 MB each
__device__ float g_x[(size_t)NTOT * C128];
__device__ float g_m[(size_t)NTOT * C128];
// GEMM scratch: 720000 * 128 floats = 368.6 MB
__device__ float g_y[(size_t)YROWS * C128];

// ---------------------------------------------------------------------------
// GEMM: Y[M x 128] = X[M x 128] @ W[128 x 128], fp32.
// Block: 256 threads, 64-row tile. W (64KB) + xT (32KB) in dynamic smem.
// Thread (warp w, lane l): rows w*8..w*8+7, cols l*4..l*4+3 -> 32 accs.
// Per k: 1 LDS.128 (W, lane-contiguous) + 2 LDS.128 (xT broadcast) + 32 FFMA.
// ---------------------------------------------------------------------------
#define TM 64
__global__ void __launch_bounds__(256) gemm128(const float* __restrict__ X,
                                               const float* __restrict__ W,
                                               float* __restrict__ Y, int M) {
    extern __shared__ float sm[];
    float* sW  = sm;               // [128][128]
    float* sXT = sm + 128 * 128;   // [128][TM]  (k-major)

    const int t = threadIdx.x;
    const int mbase = blockIdx.x * TM;

    // load W (16384 floats = 4096 float4)
    {
        const float4* Wv = (const float4*)W;
        float4* sWv = (float4*)sW;
#pragma unroll
        for (int i = 0; i < 16; i++) sWv[t + 256 * i] = Wv[t + 256 * i];
    }
    // load x tile transposed: thread t -> row t>>2, col segment (t&3)*32
    {
        int r = t >> 2;
        int cseg = (t & 3) * 32;
        int grow = mbase + r;
        const float4* xr = (const float4*)(X + (size_t)grow * C128);
#pragma unroll
        for (int i = 0; i < 8; i++) {
            float4 v;
            if (grow < M) v = xr[(cseg >> 2) + i];
            else          v = make_float4(0.f, 0.f, 0.f, 0.f);
            int c = cseg + i * 4;
            sXT[(c + 0) * TM + r] = v.x;
            sXT[(c + 1) * TM + r] = v.y;
            sXT[(c + 2) * TM + r] = v.z;
            sXT[(c + 3) * TM + r] = v.w;
        }
    }
    __syncthreads();

    const int lane = t & 31;
    const int wid  = t >> 5;
    const int c0 = lane * 4;
    const int r0 = wid * 8;

    float acc[8][4];
#pragma unroll
    for (int i = 0; i < 8; i++)
#pragma unroll
        for (int j = 0; j < 4; j++) acc[i][j] = 0.f;

#pragma unroll 8
    for (int k = 0; k < 128; k++) {
        float4 w  = *(const float4*)(sW + k * 128 + c0);
        float4 xa = *(const float4*)(sXT + k * TM + r0);
        float4 xb = *(const float4*)(sXT + k * TM + r0 + 4);
        float xr[8] = {xa.x, xa.y, xa.z, xa.w, xb.x, xb.y, xb.z, xb.w};
#pragma unroll
        for (int i = 0; i < 8; i++) {
            acc[i][0] = fmaf(xr[i], w.x, acc[i][0]);
            acc[i][1] = fmaf(xr[i], w.y, acc[i][1]);
            acc[i][2] = fmaf(xr[i], w.z, acc[i][2]);
            acc[i][3] = fmaf(xr[i], w.w, acc[i][3]);
        }
    }

#pragma unroll
    for (int i = 0; i < 8; i++) {
        int grow = mbase + r0 + i;
        if (grow < M) {
            float4 o = make_float4(acc[i][0], acc[i][1], acc[i][2], acc[i][3]);
            *(float4*)(Y + (size_t)grow * C128 + c0) = o;
        }
    }
}

// ---------------------------------------------------------------------------
// COO SPMM scatter: O[rows[e]] += vals[e] * Y[cols[e]]  (128 cols per nnz)
// One warp per nnz; lane handles 4 contiguous cols via float4 + red.v4.f32.
// ---------------------------------------------------------------------------
__global__ void __launch_bounds__(256) spmm_acc(const int* __restrict__ rows,
                                                const int* __restrict__ cols,
                                                const float* __restrict__ vals,
                                                int nnz,
                                                const float* __restrict__ Y,
                                                float* __restrict__ O) {
    int g = blockIdx.x * blockDim.x + threadIdx.x;
    int e = g >> 5;
    if (e >= nnz) return;
    int lane = g & 31;
    int r = __ldg(rows + e);
    int c = __ldg(cols + e);
    float v = __ldg(vals + e);
    float4 a = *(const float4*)(Y + (size_t)c * C128 + lane * 4);
    a.x *= v; a.y *= v; a.z *= v; a.w *= v;
    float* dst = O + (size_t)r * C128 + lane * 4;
    asm volatile("red.global.add.v4.f32 [%0], {%1, %2, %3, %4};"
                 :: "l"(dst), "f"(a.x), "f"(a.y), "f"(a.z), "f"(a.w)
                 : "memory");
}

// ---------------------------------------------------------------------------
// sigmoid: x = 1/(1+exp(-m)), float4-vectorized
// ---------------------------------------------------------------------------
__global__ void __launch_bounds__(256) sigmoid_k(const float* __restrict__ m,
                                                 float* __restrict__ x, int n4) {
    int i = blockIdx.x * blockDim.x + threadIdx.x;
    if (i >= n4) return;
    float4 v = ((const float4*)m)[i];
    v.x = 1.f / (1.f + __expf(-v.x));
    v.y = 1.f / (1.f + __expf(-v.y));
    v.z = 1.f / (1.f + __expf(-v.z));
    v.w = 1.f / (1.f + __expf(-v.w));
    ((float4*)x)[i] = v;
}

// ---------------------------------------------------------------------------
// Head: out[M x 10] = softmax(X[M x 128] @ Wout[128 x 10] + b)
// One warp per row; W in smem; warp shfl reduction; lane 0 softmax.
// ---------------------------------------------------------------------------
__global__ void __launch_bounds__(256) head_k(const float* __restrict__ X,
                                              const float* __restrict__ Wout,
                                              const float* __restrict__ bout,
                                              float* __restrict__ out, int M) {
    __shared__ float sW[128 * 10];
    __shared__ float sb[10];
    int t = threadIdx.x;
    for (int i = t; i < 1280; i += blockDim.x) sW[i] = Wout[i];
    if (t < 10) sb[t] = bout[t];
    __syncthreads();

    int warp = (blockIdx.x * blockDim.x + t) >> 5;
    int lane = t & 31;
    if (warp >= M) return;

    const float* xr = X + (size_t)warp * C128;
    float acc[10];
#pragma unroll
    for (int j = 0; j < 10; j++) acc[j] = 0.f;
#pragma unroll
    for (int i = 0; i < 4; i++) {
        int k = lane + 32 * i;
        float xv = __ldg(xr + k);
#pragma unroll
        for (int j = 0; j < 10; j++) acc[j] = fmaf(xv, sW[k * 10 + j], acc[j]);
    }
#pragma unroll
    for (int j = 0; j < 10; j++) {
#pragma unroll
        for (int o = 16; o > 0; o >>= 1)
            acc[j] += __shfl_down_sync(0xffffffffu, acc[j], o);
    }
    if (lane == 0) {
        float mx = -1e30f;
#pragma unroll
        for (int j = 0; j < 10; j++) { acc[j] += sb[j]; mx = fmaxf(mx, acc[j]); }
        float s = 0.f;
#pragma unroll
        for (int j = 0; j < 10; j++) { acc[j] = __expf(acc[j] - mx); s += acc[j]; }
        float inv = 1.f / s;
#pragma unroll
        for (int j = 0; j < 10; j++) out[(size_t)warp * 10 + j] = acc[j] * inv;
    }
}

// ---------------------------------------------------------------------------
// Host orchestration
// ---------------------------------------------------------------------------
extern "C" void kernel_launch(void* const* d_in, const int* in_sizes, int n_in,
                              void* d_out, int out_size) {
    const int N[4]      = {N0, N1, N2, N3};
    const int ROWOFF[4] = {0, 40000, 160000, 240000};       // into g_x / g_m
    const int ADJNNZ[4] = {320000, 960000, 640000, 160000};
    const int INCNNZ[3] = {240000, 240000, 80000};

    // g_y scratch row offsets
    const int SAME_OFF[4] = {0, 40000, 160000, 240000};         // sizes N[r]
    const int H2L_OFF[3]  = {260000, 380000, 460000};           // sizes N[r+1]
    const int L2H_OFF[3]  = {480000, 520000, 640000};           // r=1..3, sizes N[r-1]

    const float* x_in[4] = {(const float*)d_in[0], (const float*)d_in[1],
                            (const float*)d_in[2], (const float*)d_in[3]};
    const int*   adj_row[4]; const int* adj_col[4]; const float* adj_val[4];
    for (int r = 0; r < 4; r++) {
        adj_row[r] = (const int*)d_in[4 + 3 * r];
        adj_col[r] = (const int*)d_in[5 + 3 * r];
        adj_val[r] = (const float*)d_in[6 + 3 * r];
    }
    const int* inc_row[3]; const int* inc_col[3]; const float* inc_val[3];
    for (int i = 0; i < 3; i++) {
        inc_row[i] = (const int*)d_in[16 + 3 * i];
        inc_col[i] = (const int*)d_in[17 + 3 * i];
        inc_val[i] = (const float*)d_in[18 + 3 * i];
    }
    const float* W_same = (const float*)d_in[25];  // (2,4,128,128)
    const float* W_h2l  = (const float*)d_in[26];  // (2,3,128,128)
    const float* W_l2h  = (const float*)d_in[27];  // (2,3,128,128)
    const float* W_out  = (const float*)d_in[28];  // (128,10)
    const float* b_out  = (const float*)d_in[29];  // (10)
    float* out = (float*)d_out;

    float *gx, *gm, *gy;
    cudaGetSymbolAddress((void**)&gx, g_x);
    cudaGetSymbolAddress((void**)&gm, g_m);
    cudaGetSymbolAddress((void**)&gy, g_y);

    const int GEMM_SMEM = (128 * 128 + 128 * TM) * 4;  // 96 KB
    cudaFuncSetAttribute(gemm128, cudaFuncAttributeMaxDynamicSharedMemorySize,
                         GEMM_SMEM);

    const int WMAT = 128 * 128;

    for (int l = 0; l < 2; l++) {
        const float* xs[4];
        for (int r = 0; r < 4; r++)
            xs[r] = (l == 0) ? x_in[r] : (gx + (size_t)ROWOFF[r] * C128);

        // phase A: dense GEMMs into scratch
        for (int r = 0; r < 4; r++) {
            gemm128<<<(N[r] + TM - 1) / TM, 256, GEMM_SMEM>>>(
                xs[r], W_same + (size_t)(l * 4 + r) * WMAT,
                gy + (size_t)SAME_OFF[r] * C128, N[r]);
        }
        for (int r = 0; r < 3; r++) {  // h2l for rank r uses x_{r+1}
            gemm128<<<(N[r + 1] + TM - 1) / TM, 256, GEMM_SMEM>>>(
                xs[r + 1], W_h2l + (size_t)(l * 3 + r) * WMAT,
                gy + (size_t)H2L_OFF[r] * C128, N[r + 1]);
        }
        for (int r = 1; r < 4; r++) {  // l2h for rank r uses x_{r-1}
            gemm128<<<(N[r - 1] + TM - 1) / TM, 256, GEMM_SMEM>>>(
                xs[r - 1], W_l2h + (size_t)(l * 3 + (r - 1)) * WMAT,
                gy + (size_t)L2H_OFF[r - 1] * C128, N[r - 1]);
        }

        // phase B: zero accumulator
        cudaMemsetAsync(gm, 0, (size_t)NTOT * C128 * sizeof(float));

        // phase C: scatter-add SPMMs
        for (int r = 0; r < 4; r++) {
            int blocks = (ADJNNZ[r] * 32 + 255) / 256;
            spmm_acc<<<blocks, 256>>>(adj_row[r], adj_col[r], adj_val[r],
                                      ADJNNZ[r],
                                      gy + (size_t)SAME_OFF[r] * C128,
                                      gm + (size_t)ROWOFF[r] * C128);
        }
        for (int r = 0; r < 3; r++) {  // h2l: out[irow] += ival * y[icol]
            int blocks = (INCNNZ[r] * 32 + 255) / 256;
            spmm_acc<<<blocks, 256>>>(inc_row[r], inc_col[r], inc_val[r],
                                      INCNNZ[r],
                                      gy + (size_t)H2L_OFF[r] * C128,
                                      gm + (size_t)ROWOFF[r] * C128);
        }
        for (int r = 1; r < 4; r++) {  // l2h: out[icol] += ival * y[irow]
            int i = r - 1;
            int blocks = (INCNNZ[i] * 32 + 255) / 256;
            spmm_acc<<<blocks, 256>>>(inc_col[i], inc_row[i], inc_val[i],
                                      INCNNZ[i],
                                      gy + (size_t)L2H_OFF[i] * C128,
                                      gm + (size_t)ROWOFF[r] * C128);
        }

        // phase D: sigmoid -> g_x
        {
            int n4 = NTOT * C128 / 4;
            sigmoid_k<<<(n4 + 255) / 256, 256>>>(gm, gx, n4);
        }
    }

    // head: softmax(x0 @ W_out + b_out)
    {
        int blocks = (N0 * 32 + 255) / 256;  // warp per row
        head_k<<<blocks, 256>>>(gx /* rank0 at offset 0 */, W_out, b_out, out, N0);
    }
}

// round 9
// speedup vs baseline: 1.4497x; 1.4497x over previous
#include <cuda_runtime.h>
#include <cuda_bf16.h>
#include <cstdint>

// ---------------------------------------------------------------------------
// SCCN forward: 4 ranks, C=128, L=2 layers, sigmoid update, softmax head.
// R7: dense GEMMs via legacy mma.sync tf32 (base sm_103-legal PTX; tcgen05 is
//     rejected by this harness's .target). Weight-concatenated: one kernel per
//     source rank computes x_r @ {2..3 weight mats}, x read once.
// ---------------------------------------------------------------------------

#define C128 128

static const int N0 = 40000, N1 = 120000, N2 = 80000, N3 = 20000;
static const int NTOT = 260000;
static const int YROWS = 720000;

__device__ float g_x[(size_t)NTOT * C128];
__device__ float g_m[(size_t)NTOT * C128];
__device__ float g_y[(size_t)YROWS * C128];

// ------------------------- helpers -----------------------------------------
__device__ __forceinline__ uint32_t f2tf32(float f) {
    uint32_t r;
    asm("cvt.rna.tf32.f32 %0, %1;" : "=r"(r) : "f"(f));
    return r;
}

// m16n8k8 tf32 mma, C/D fp32. A row-major frag, B col-major frag.
__device__ __forceinline__ void mma_tf32(float* c, const uint32_t* a,
                                         uint32_t b0, uint32_t b1) {
    asm volatile(
        "mma.sync.aligned.m16n8k8.row.col.f32.tf32.tf32.f32 "
        "{%0,%1,%2,%3}, {%4,%5,%6,%7}, {%8,%9}, {%0,%1,%2,%3};"
        : "+f"(c[0]), "+f"(c[1]), "+f"(c[2]), "+f"(c[3])
        : "r"(a[0]), "r"(a[1]), "r"(a[2]), "r"(a[3]), "r"(b0), "r"(b1));
}

// ---------------------------------------------------------------------------
// gemm_mma: for source X[M x 128], compute Y_c = X @ W_c for c < nc (nc<=3).
// Persistent CTAs. W chunks staged once per CTA in smem as tf32, pre-packed
// so a B fragment (b0=B[k][n], b1=B[k+4][n]) is one conflict-free LDS.64:
//   sWp[c][(kc*4+q)*132 + n] = { W[kc*8+q][n], W[kc*8+q+4][n] }   (float2)
// Block = 256 thr / 8 warps, 256-row tiles, warp covers 32 rows (2 m16 blocks
// sharing each B fragment). A fragments from global with cvt.rna.tf32.
// ---------------------------------------------------------------------------
#define WCHUNK (64 * 132)  // float2 elements per weight chunk

__global__ void __launch_bounds__(256) gemm_mma(
    const float* __restrict__ X, int M, int nc,
    const float* __restrict__ W0, const float* __restrict__ W1,
    const float* __restrict__ W2,
    float* __restrict__ Y0, float* __restrict__ Y1, float* __restrict__ Y2) {
    extern __shared__ __align__(16) float2 sWp[];
    const float* Ws[3] = {W0, W1, W2};
    float* Ys[3] = {Y0, Y1, Y2};
    const int t = threadIdx.x;

    // stage weights (once per CTA; persistent loop follows)
    for (int c = 0; c < nc; c++) {
        const float* W = Ws[c];
        float2* dst = sWp + c * WCHUNK;
        for (int i = t; i < 8192; i += 256) {
            int kcq = i >> 7, n = i & 127;
            int k_lo = (kcq >> 2) * 8 + (kcq & 3);
            float2 v;
            v.x = __uint_as_float(f2tf32(__ldg(W + k_lo * C128 + n)));
            v.y = __uint_as_float(f2tf32(__ldg(W + (k_lo + 4) * C128 + n)));
            dst[kcq * 132 + n] = v;
        }
    }
    __syncthreads();

    const int lane = t & 31, wid = t >> 5;
    const int q = lane & 3, p = lane >> 2;
    const int tiles = (M + 255) >> 8;

    for (int tile = blockIdx.x; tile < tiles; tile += gridDim.x) {
        const int rbase = (tile << 8) + (wid << 5);
        const int r0 = rbase + p;
        const int rr[4] = {r0, r0 + 8, r0 + 16, r0 + 24};
        const bool g[4] = {rr[0] < M, rr[1] < M, rr[2] < M, rr[3] < M};

        // A fragments: 2 row-blocks x 16 k-chunks x 4 regs = 128 regs
        uint32_t A[2][16][4];
#pragma unroll
        for (int b = 0; b < 2; b++) {
            const float* x0 = X + (size_t)rr[b * 2] * C128 + q;
            const float* x1 = X + (size_t)rr[b * 2 + 1] * C128 + q;
#pragma unroll
            for (int kc = 0; kc < 16; kc++) {
                int col = kc * 8;
                A[b][kc][0] = g[b * 2]     ? f2tf32(__ldg(x0 + col))     : 0u;
                A[b][kc][1] = g[b * 2 + 1] ? f2tf32(__ldg(x1 + col))     : 0u;
                A[b][kc][2] = g[b * 2]     ? f2tf32(__ldg(x0 + col + 4)) : 0u;
                A[b][kc][3] = g[b * 2 + 1] ? f2tf32(__ldg(x1 + col + 4)) : 0u;
            }
        }

#pragma unroll 1
        for (int c = 0; c < nc; c++) {
            const float2* Wp = sWp + c * WCHUNK;
            float* Y = Ys[c];
#pragma unroll 1
            for (int n0 = 0; n0 < 128; n0 += 8) {
                float acc0[4] = {0.f, 0.f, 0.f, 0.f};
                float acc1[4] = {0.f, 0.f, 0.f, 0.f};
#pragma unroll
                for (int kc = 0; kc < 16; kc++) {
                    float2 bb = Wp[(kc * 4 + q) * 132 + n0 + p];
                    uint32_t b0 = __float_as_uint(bb.x);
                    uint32_t b1 = __float_as_uint(bb.y);
                    mma_tf32(acc0, A[0][kc], b0, b1);
                    mma_tf32(acc1, A[1][kc], b0, b1);
                }
                const int col = n0 + q * 2;
                if (g[0]) *(float2*)(Y + (size_t)rr[0] * C128 + col) =
                              make_float2(acc0[0], acc0[1]);
                if (g[1]) *(float2*)(Y + (size_t)rr[1] * C128 + col) =
                              make_float2(acc0[2], acc0[3]);
                if (g[2]) *(float2*)(Y + (size_t)rr[2] * C128 + col) =
                              make_float2(acc1[0], acc1[1]);
                if (g[3]) *(float2*)(Y + (size_t)rr[3] * C128 + col) =
                              make_float2(acc1[2], acc1[3]);
            }
        }
    }
}

// ---------------------------------------------------------------------------
// COO SPMM scatter: O[rows[e]] += vals[e] * Y[cols[e]]  (warp per nnz)
// ---------------------------------------------------------------------------
__global__ void __launch_bounds__(256) spmm_acc(const int* __restrict__ rows,
                                                const int* __restrict__ cols,
                                                const float* __restrict__ vals,
                                                int nnz,
                                                const float* __restrict__ Y,
                                                float* __restrict__ O) {
    int gthr = blockIdx.x * blockDim.x + threadIdx.x;
    int e = gthr >> 5;
    if (e >= nnz) return;
    int lane = gthr & 31;
    int r = __ldg(rows + e);
    int c = __ldg(cols + e);
    float v = __ldg(vals + e);
    float4 a = *(const float4*)(Y + (size_t)c * C128 + lane * 4);
    a.x *= v; a.y *= v; a.z *= v; a.w *= v;
    float* dst = O + (size_t)r * C128 + lane * 4;
    asm volatile("red.global.add.v4.f32 [%0], {%1, %2, %3, %4};"
                 :: "l"(dst), "f"(a.x), "f"(a.y), "f"(a.z), "f"(a.w)
                 : "memory");
}

// ---------------------------------------------------------------------------
__global__ void __launch_bounds__(256) sigmoid_k(const float* __restrict__ m,
                                                 float* __restrict__ x, int n4) {
    int i = blockIdx.x * blockDim.x + threadIdx.x;
    if (i >= n4) return;
    float4 v = ((const float4*)m)[i];
    v.x = 1.f / (1.f + __expf(-v.x));
    v.y = 1.f / (1.f + __expf(-v.y));
    v.z = 1.f / (1.f + __expf(-v.z));
    v.w = 1.f / (1.f + __expf(-v.w));
    ((float4*)x)[i] = v;
}

// ---------------------------------------------------------------------------
__global__ void __launch_bounds__(256) head_k(const float* __restrict__ X,
                                              const float* __restrict__ Wout,
                                              const float* __restrict__ bout,
                                              float* __restrict__ out, int M) {
    __shared__ float sW[128 * 10];
    __shared__ float sb[10];
    int t = threadIdx.x;
    for (int i = t; i < 1280; i += blockDim.x) sW[i] = Wout[i];
    if (t < 10) sb[t] = bout[t];
    __syncthreads();

    int warp = (blockIdx.x * blockDim.x + t) >> 5;
    int lane = t & 31;
    if (warp >= M) return;

    const float* xr = X + (size_t)warp * C128;
    float acc[10];
#pragma unroll
    for (int j = 0; j < 10; j++) acc[j] = 0.f;
#pragma unroll
    for (int i = 0; i < 4; i++) {
        int k = lane + 32 * i;
        float xv = __ldg(xr + k);
#pragma unroll
        for (int j = 0; j < 10; j++) acc[j] = fmaf(xv, sW[k * 10 + j], acc[j]);
    }
#pragma unroll
    for (int j = 0; j < 10; j++) {
#pragma unroll
        for (int o = 16; o > 0; o >>= 1)
            acc[j] += __shfl_down_sync(0xffffffffu, acc[j], o);
    }
    if (lane == 0) {
        float mx = -1e30f;
#pragma unroll
        for (int j = 0; j < 10; j++) { acc[j] += sb[j]; mx = fmaxf(mx, acc[j]); }
        float s = 0.f;
#pragma unroll
        for (int j = 0; j < 10; j++) { acc[j] = __expf(acc[j] - mx); s += acc[j]; }
        float inv = 1.f / s;
#pragma unroll
        for (int j = 0; j < 10; j++) out[(size_t)warp * 10 + j] = acc[j] * inv;
    }
}

// ---------------------------------------------------------------------------
// Host orchestration
// ---------------------------------------------------------------------------
extern "C" void kernel_launch(void* const* d_in, const int* in_sizes, int n_in,
                              void* d_out, int out_size) {
    const int N[4]      = {N0, N1, N2, N3};
    const int ROWOFF[4] = {0, 40000, 160000, 240000};
    const int ADJNNZ[4] = {320000, 960000, 640000, 160000};
    const int INCNNZ[3] = {240000, 240000, 80000};

    const int SAME_OFF[4] = {0, 40000, 160000, 240000};
    const int H2L_OFF[3]  = {260000, 380000, 460000};  // rank r h2l (from x_{r+1})
    const int L2H_OFF[3]  = {480000, 520000, 640000};  // rank r+1 l2h (from x_r)

    const float* x_in[4] = {(const float*)d_in[0], (const float*)d_in[1],
                            (const float*)d_in[2], (const float*)d_in[3]};
    const int*   adj_row[4]; const int* adj_col[4]; const float* adj_val[4];
    for (int r = 0; r < 4; r++) {
        adj_row[r] = (const int*)d_in[4 + 3 * r];
        adj_col[r] = (const int*)d_in[5 + 3 * r];
        adj_val[r] = (const float*)d_in[6 + 3 * r];
    }
    const int* inc_row[3]; const int* inc_col[3]; const float* inc_val[3];
    for (int i = 0; i < 3; i++) {
        inc_row[i] = (const int*)d_in[16 + 3 * i];
        inc_col[i] = (const int*)d_in[17 + 3 * i];
        inc_val[i] = (const float*)d_in[18 + 3 * i];
    }
    const float* W_same = (const float*)d_in[25];
    const float* W_h2l  = (const float*)d_in[26];
    const float* W_l2h  = (const float*)d_in[27];
    const float* W_out  = (const float*)d_in[28];
    const float* b_out  = (const float*)d_in[29];
    float* out = (float*)d_out;

    float *gx, *gm, *gy;
    cudaGetSymbolAddress((void**)&gx, g_x);
    cudaGetSymbolAddress((void**)&gm, g_m);
    cudaGetSymbolAddress((void**)&gy, g_y);

    const int MAX_SMEM = 3 * WCHUNK * (int)sizeof(float2);  // 202752 B
    cudaFuncSetAttribute(gemm_mma, cudaFuncAttributeMaxDynamicSharedMemorySize,
                         MAX_SMEM);

    const int WMAT = 128 * 128;
    auto launch = [&](const float* X, int M, int nc,
                      const float* w0, const float* w1, const float* w2,
                      float* y0, float* y1, float* y2) {
        int tiles = (M + 255) / 256;
        int grid = tiles < 148 ? tiles : 148;
        gemm_mma<<<grid, 256, nc * WCHUNK * (int)sizeof(float2)>>>(
            X, M, nc, w0, w1, w2, y0, y1, y2);
    };

    for (int l = 0; l < 2; l++) {
        const float* xs[4];
        for (int r = 0; r < 4; r++)
            xs[r] = (l == 0) ? x_in[r] : (gx + (size_t)ROWOFF[r] * C128);

        // phase A: weight-concatenated GEMMs, one launch per source rank
        // src x0: same[0]; l2h[0] (feeds rank1)
        launch(xs[0], N[0], 2,
               W_same + (size_t)(l * 4 + 0) * WMAT,
               W_l2h  + (size_t)(l * 3 + 0) * WMAT, nullptr,
               gy + (size_t)SAME_OFF[0] * C128,
               gy + (size_t)L2H_OFF[0] * C128, nullptr);
        // src x1: same[1]; h2l[0] (feeds rank0); l2h[1] (feeds rank2)
        launch(xs[1], N[1], 3,
               W_same + (size_t)(l * 4 + 1) * WMAT,
               W_h2l  + (size_t)(l * 3 + 0) * WMAT,
               W_l2h  + (size_t)(l * 3 + 1) * WMAT,
               gy + (size_t)SAME_OFF[1] * C128,
               gy + (size_t)H2L_OFF[0] * C128,
               gy + (size_t)L2H_OFF[1] * C128);
        // src x2: same[2]; h2l[1] (feeds rank1); l2h[2] (feeds rank3)
        launch(xs[2], N[2], 3,
               W_same + (size_t)(l * 4 + 2) * WMAT,
               W_h2l  + (size_t)(l * 3 + 1) * WMAT,
               W_l2h  + (size_t)(l * 3 + 2) * WMAT,
               gy + (size_t)SAME_OFF[2] * C128,
               gy + (size_t)H2L_OFF[1] * C128,
               gy + (size_t)L2H_OFF[2] * C128);
        // src x3: same[3]; h2l[2] (feeds rank2)
        launch(xs[3], N[3], 2,
               W_same + (size_t)(l * 4 + 3) * WMAT,
               W_h2l  + (size_t)(l * 3 + 2) * WMAT, nullptr,
               gy + (size_t)SAME_OFF[3] * C128,
               gy + (size_t)H2L_OFF[2] * C128, nullptr);

        // phase B: zero accumulator
        cudaMemsetAsync(gm, 0, (size_t)NTOT * C128 * sizeof(float));

        // phase C: scatter-add SPMMs
        for (int r = 0; r < 4; r++) {
            int blocks = (ADJNNZ[r] * 32 + 255) / 256;
            spmm_acc<<<blocks, 256>>>(adj_row[r], adj_col[r], adj_val[r],
                                      ADJNNZ[r],
                                      gy + (size_t)SAME_OFF[r] * C128,
                                      gm + (size_t)ROWOFF[r] * C128);
        }
        for (int r = 0; r < 3; r++) {
            int blocks = (INCNNZ[r] * 32 + 255) / 256;
            spmm_acc<<<blocks, 256>>>(inc_row[r], inc_col[r], inc_val[r],
                                      INCNNZ[r],
                                      gy + (size_t)H2L_OFF[r] * C128,
                                      gm + (size_t)ROWOFF[r] * C128);
        }
        for (int r = 1; r < 4; r++) {
            int i = r - 1;
            int blocks = (INCNNZ[i] * 32 + 255) / 256;
            spmm_acc<<<blocks, 256>>>(inc_col[i], inc_row[i], inc_val[i],
                                      INCNNZ[i],
                                      gy + (size_t)L2H_OFF[i] * C128,
                                      gm + (size_t)ROWOFF[r] * C128);
        }

        // phase D: sigmoid -> g_x
        int n4 = NTOT * C128 / 4;
        sigmoid_k<<<(n4 + 255) / 256, 256>>>(gm, gx, n4);
    }

    // head
    int blocks = (N0 * 32 + 255) / 256;
    head_k<<<blocks, 256>>>(gx, W_out, b_out, out, N0);
}